// round 9
// baseline (speedup 1.0000x reference)
#include <cuda_runtime.h>
#include <cuda_fp16.h>
#include <cstdint>
#include <cstddef>

#define NN   65536
#define F    512
#define KNN  16
#define NOUT 1024

#define BM 128
#define BN 256
#define BK 64
#define STAGES 4
#define GEMM_THREADS 256           // 8 warps: 2 (m) x 4 (n), warp tile 64x64
#define NKTILES (F / BK)           // 8

// smem row: 64 fp16 data + 8 pad = 72 elems = 144B
#define ROWB 144
#define A_TILE_BYTES (BM * ROWB)               // 18432
#define B_TILE_BYTES (BN * ROWB)               // 36864
#define STAGE_BYTES  (A_TILE_BYTES + B_TILE_BYTES)  // 55296
#define SM_TOTAL (STAGES * STAGE_BYTES)        // 221184

// ---------------- scratch (__device__ globals) ------------------------------
__device__ __align__(1024) float   g_hdst[(size_t)NN * F];     // 128MB (phi-theta)
__device__ __align__(1024) __half  g_theta16[(size_t)NN * F];  // 64MB
__device__ __align__(1024) __half  g_A16[(size_t)NN * F];      // 64MB
__device__ __align__(1024) __half  g_BT16[(size_t)NOUT * F];   // 1MB
__device__ int g_idx_is64;

// ---------------- helpers ----------------------------------------------------
__device__ __forceinline__ uint32_t smem_to_u32(const void* p) {
    uint32_t a;
    asm("{ .reg .u64 t; cvta.to.shared.u64 t, %1; cvt.u32.u64 %0, t; }"
        : "=r"(a) : "l"(p));
    return a;
}
__device__ __forceinline__ void cp16(uint32_t dst, const void* src) {
    asm volatile("cp.async.cg.shared.global [%0], [%1], 16;" :: "r"(dst), "l"(src));
}
__device__ __forceinline__ void ldmatrix_x4(uint32_t* r, uint32_t addr) {
    asm volatile("ldmatrix.sync.aligned.m8n8.x4.shared.b16 {%0,%1,%2,%3}, [%4];"
                 : "=r"(r[0]), "=r"(r[1]), "=r"(r[2]), "=r"(r[3]) : "r"(addr));
}
__device__ __forceinline__ void mma_f16(float* c, const uint32_t* a, const uint32_t* b) {
    asm volatile(
        "mma.sync.aligned.m16n8k16.row.col.f32.f16.f16.f32 "
        "{%0,%1,%2,%3}, {%4,%5,%6,%7}, {%8,%9}, {%0,%1,%2,%3};"
        : "+f"(c[0]), "+f"(c[1]), "+f"(c[2]), "+f"(c[3])
        : "r"(a[0]), "r"(a[1]), "r"(a[2]), "r"(a[3]), "r"(b[0]), "r"(b[1]));
}

// ---------------- index width detection --------------------------------------
__global__ void detect_idx_kernel(const unsigned int* __restrict__ w) {
    int is64 = 1;
    for (int i = 1; i < 512; i += 2)
        if (w[i] != 0u) { is64 = 0; break; }
    g_idx_is64 = is64;
}

// ---------------- feat -> fp16 ------------------------------------------------
__global__ __launch_bounds__(256) void convert_A_kernel(const float* __restrict__ A) {
    const size_t i = (size_t)blockIdx.x * 256 + threadIdx.x;
    const float4 v = reinterpret_cast<const float4*>(A)[i];
    __half2 h0 = __floats2half2_rn(v.x, v.y);
    __half2 h1 = __floats2half2_rn(v.z, v.w);
    uint2 packed;
    packed.x = *reinterpret_cast<uint32_t*>(&h0);
    packed.y = *reinterpret_cast<uint32_t*>(&h1);
    reinterpret_cast<uint2*>(g_A16)[i] = packed;
}

// ---------------- W -> B^T fp16: rows [0,512)=Wt^T, [512,1024)=(Wp-Wt)^T ------
__global__ __launch_bounds__(256) void convert_W_kernel(const float* __restrict__ Wt,
                                                        const float* __restrict__ Wp) {
    const int idx = blockIdx.x * 256 + threadIdx.x;   // [0, 1024*512)
    const int n = idx >> 9;
    const int k = idx & 511;
    const int nc = n & 511;
    float w;
    if (n < 512) w = Wt[(size_t)k * 512 + nc];
    else         w = Wp[(size_t)k * 512 + nc] - Wt[(size_t)k * 512 + nc];
    g_BT16[(size_t)n * F + k] = __float2half_rn(w);
}

// ---------------- HMMA dual GEMM ----------------------------------------------
// C[65536 x 1024] = A16 @ [Wt | Wp-Wt], fp16 in, fp32 acc
__device__ __forceinline__ void load_tile(uint32_t sm_base, int stage, int t,
                                          int m0, int n0, int tid) {
    const int kc = t * BK;
    const uint32_t smA = sm_base + stage * STAGE_BYTES;
    const uint32_t smB = smA + A_TILE_BYTES;
#pragma unroll
    for (int i = 0; i < 4; i++) {               // A: 128 rows x 8 chunks = 1024
        const int q = tid + i * GEMM_THREADS;
        const int r = q >> 3;
        const int c = q & 7;
        cp16(smA + r * ROWB + c * 16,
             g_A16 + (size_t)(m0 + r) * F + kc + c * 8);
    }
#pragma unroll
    for (int i = 0; i < 8; i++) {               // B: 256 rows x 8 chunks = 2048
        const int q = tid + i * GEMM_THREADS;
        const int r = q >> 3;
        const int c = q & 7;
        cp16(smB + r * ROWB + c * 16,
             g_BT16 + (size_t)(n0 + r) * F + kc + c * 8);
    }
    asm volatile("cp.async.commit_group;" ::: "memory");
}

__global__ __launch_bounds__(GEMM_THREADS, 1) void gemm_kernel() {
    extern __shared__ __align__(128) char smem[];
    const uint32_t sm_base = smem_to_u32(smem);
    const int tid = threadIdx.x;
    const int wid = tid >> 5;
    const int lid = tid & 31;

    // block swizzle: groups of 32 m-blocks sweep all 4 n-blocks (A stays in L2)
    const int bid   = blockIdx.x;
    const int group = bid >> 7;            // / (32*4)
    const int inner = bid & 127;
    const int n_blk = inner >> 5;
    const int m_blk = (group << 5) | (inner & 31);
    const int m0 = m_blk * BM;
    const int n0 = n_blk * BN;

    // warp layout: 2 (m) x 4 (n); warp tile 64m x 64n
    const int wm0 = (wid >> 2) * 64;
    const int wn0 = (wid & 3) * 64;

    float acc[4][8][4];
#pragma unroll
    for (int i = 0; i < 4; i++)
#pragma unroll
        for (int j = 0; j < 8; j++)
#pragma unroll
            for (int q = 0; q < 4; q++) acc[i][j][q] = 0.f;

    load_tile(sm_base, 0, 0, m0, n0, tid);
    load_tile(sm_base, 1, 1, m0, n0, tid);
    load_tile(sm_base, 2, 2, m0, n0, tid);

    const int a_row_off = wm0 + (lid & 15);
    const int a_col_off = (lid >> 4) * 8;
    const int b_row_off = wn0 + ((lid & 16) >> 1) + (lid & 7);
    const int b_col_off = ((lid & 8) ? 8 : 0);

    for (int t = 0; t < NKTILES; t++) {
        const int st = t & 3;
        // retire group t: outstanding = min(3, NKTILES - t)
        if (t < NKTILES - 2)       asm volatile("cp.async.wait_group 2;" ::: "memory");
        else if (t == NKTILES - 2) asm volatile("cp.async.wait_group 1;" ::: "memory");
        else                       asm volatile("cp.async.wait_group 0;" ::: "memory");
        // all warps finished t-1 -> slot (t+3)&3 == (t-1)&3 free
        __syncthreads();

        if (t + 3 < NKTILES)
            load_tile(sm_base, (t + 3) & 3, t + 3, m0, n0, tid);

        const uint32_t smA = sm_base + st * STAGE_BYTES;
        const uint32_t smB = smA + A_TILE_BYTES;

        // fragment double buffer over 4 ks steps
        uint32_t a[2][4][4], b[2][8][2];
        {
#pragma unroll
            for (int i = 0; i < 4; i++)
                ldmatrix_x4(a[0][i], smA + (a_row_off + i * 16) * ROWB
                                         + a_col_off * 2);
#pragma unroll
            for (int j2 = 0; j2 < 4; j2++) {
                uint32_t r[4];
                ldmatrix_x4(r, smB + (b_row_off + j2 * 16) * ROWB
                                   + b_col_off * 2);
                b[0][j2 * 2 + 0][0] = r[0]; b[0][j2 * 2 + 0][1] = r[1];
                b[0][j2 * 2 + 1][0] = r[2]; b[0][j2 * 2 + 1][1] = r[3];
            }
        }
#pragma unroll
        for (int ks = 0; ks < 4; ks++) {
            const int cur = ks & 1;
            if (ks < 3) {
                const int nxt = cur ^ 1;
                const int col = (ks + 1) * 16;
#pragma unroll
                for (int i = 0; i < 4; i++)
                    ldmatrix_x4(a[nxt][i], smA + (a_row_off + i * 16) * ROWB
                                               + (col + a_col_off) * 2);
#pragma unroll
                for (int j2 = 0; j2 < 4; j2++) {
                    uint32_t r[4];
                    ldmatrix_x4(r, smB + (b_row_off + j2 * 16) * ROWB
                                       + (col + b_col_off) * 2);
                    b[nxt][j2 * 2 + 0][0] = r[0]; b[nxt][j2 * 2 + 0][1] = r[1];
                    b[nxt][j2 * 2 + 1][0] = r[2]; b[nxt][j2 * 2 + 1][1] = r[3];
                }
            }
#pragma unroll
            for (int i = 0; i < 4; i++)
#pragma unroll
                for (int j = 0; j < 8; j++)
                    mma_f16(acc[i][j], a[cur][i], b[cur][j]);
        }
    }

    // epilogue: theta blocks -> fp16 mirror; hdst blocks -> fp32
    const bool is_theta = (n0 < 512);
    const int nc0 = n0 & 511;
    const int er = lid >> 2;
    const int ec = (lid & 3) * 2;
#pragma unroll
    for (int i = 0; i < 4; i++) {
#pragma unroll
        for (int j = 0; j < 8; j++) {
            const int m = m0 + wm0 + i * 16 + er;
            const int n = nc0 + wn0 + j * 8 + ec;
            float2 v0 = make_float2(acc[i][j][0], acc[i][j][1]);
            float2 v1 = make_float2(acc[i][j][2], acc[i][j][3]);
            if (is_theta) {
                *reinterpret_cast<__half2*>(&g_theta16[(size_t)m * F + n]) =
                    __float22half2_rn(v0);
                *reinterpret_cast<__half2*>(&g_theta16[(size_t)(m + 8) * F + n]) =
                    __float22half2_rn(v1);
            } else {
                *reinterpret_cast<float2*>(&g_hdst[(size_t)m * F + n])       = v0;
                *reinterpret_cast<float2*>(&g_hdst[(size_t)(m + 8) * F + n]) = v1;
            }
        }
    }
}

// ---------------- gather + max + add -------------------------------------------
// out[n][c] = max_j theta16[src[n][j]][c] + hdst[n][c]
__global__ __launch_bounds__(128) void gather_max_kernel(
    const void* __restrict__ src, float* __restrict__ out)
{
    const int n  = blockIdx.x;
    const int c4 = threadIdx.x;            // 0..127: 4 features each

    __shared__ unsigned int sidx[KNN];
    if (threadIdx.x < KNN) {
        if (g_idx_is64) {
            sidx[threadIdx.x] = (unsigned int)((const unsigned long long*)src)
                                    [(size_t)n * KNN + threadIdx.x] & 0xFFFFu;
        } else {
            sidx[threadIdx.x] = ((const unsigned int*)src)
                                    [(size_t)n * KNN + threadIdx.x] & 0xFFFFu;
        }
    }
    __syncthreads();

    const uint2* __restrict__ t16 = reinterpret_cast<const uint2*>(g_theta16);

    uint2 raw = t16[(size_t)sidx[0] * (F / 4) + c4];
    __half2 m0 = *reinterpret_cast<__half2*>(&raw.x);
    __half2 m1 = *reinterpret_cast<__half2*>(&raw.y);
#pragma unroll
    for (int j = 1; j < KNN; j++) {
        uint2 r = t16[(size_t)sidx[j] * (F / 4) + c4];
        m0 = __hmax2(m0, *reinterpret_cast<__half2*>(&r.x));
        m1 = __hmax2(m1, *reinterpret_cast<__half2*>(&r.y));
    }

    const float4 hd = reinterpret_cast<const float4*>(g_hdst)[(size_t)n * (F / 4) + c4];

    const float2 f0 = __half22float2(m0);
    const float2 f1 = __half22float2(m1);
    float4 r;
    r.x = f0.x + hd.x; r.y = f0.y + hd.y;
    r.z = f1.x + hd.z; r.w = f1.y + hd.w;
    reinterpret_cast<float4*>(out)[(size_t)n * (F / 4) + c4] = r;
}

// ---------------------------------------------------------------------------------
extern "C" void kernel_launch(void* const* d_in, const int* in_sizes, int n_in,
                              void* d_out, int out_size)
{
    const void*  src  = nullptr;
    const float* feat = nullptr;
    const float* Wt   = nullptr;
    const float* Wp   = nullptr;

    for (int i = 0; i < n_in; i++) {
        const int s = in_sizes[i];
        if (s == NN * KNN)      src  = d_in[i];
        else if (s == NN * F)   feat = (const float*)d_in[i];
        else if (s == F * F) {
            if (!Wt) Wt = (const float*)d_in[i];
            else     Wp = (const float*)d_in[i];
        }
    }

    cudaFuncSetAttribute(gemm_kernel,
                         cudaFuncAttributeMaxDynamicSharedMemorySize, SM_TOTAL);

    detect_idx_kernel<<<1, 1>>>((const unsigned int*)src);
    convert_A_kernel<<<(NN * (F / 4)) / 256, 256>>>(feat);
    convert_W_kernel<<<(NOUT * F) / 256, 256>>>(Wt, Wp);
    gemm_kernel<<<(NN / BM) * (NOUT / BN), GEMM_THREADS, SM_TOTAL>>>();
    gather_max_kernel<<<NN, 128>>>(src, (float*)d_out);
}

// round 10
// speedup vs baseline: 1.0566x; 1.0566x over previous
#include <cuda_runtime.h>
#include <cuda_fp16.h>
#include <cstdint>
#include <cstddef>

#define NN   65536
#define F    512
#define KNN  16
#define NOUT 1024

#define BM 128
#define BN 128
#define BK 64
#define STAGES 3
#define GEMM_THREADS 128           // 4 warps, 2x2, warp tile 64x64
#define KSTEPS 8                   // k-tiles per output tile (512/64)
#define NTILES 4096                // (65536/128) * (1024/128)
#define NCTA   296                 // 2 per SM * 148 SMs, persistent

// smem row: 64 fp16 data + 8 pad = 72 elems = 144B
#define ROWB 144
#define TILE_BYTES (128 * ROWB)            // 18432
#define STAGE_BYTES (2 * TILE_BYTES)       // 36864 (A + B)
#define SM_TOTAL (STAGES * STAGE_BYTES)    // 110592  (x2 CTAs = 221KB/SM)

// ---------------- scratch (__device__ globals) ------------------------------
__device__ __align__(1024) float   g_hdst[(size_t)NN * F];     // 128MB (phi-theta)
__device__ __align__(1024) __half  g_theta16[(size_t)NN * F];  // 64MB
__device__ __align__(1024) __half  g_A16[(size_t)NN * F];      // 64MB
__device__ __align__(1024) __half  g_BT16[(size_t)NOUT * F];   // 1MB
__device__ int g_idx_is64;

// ---------------- helpers ----------------------------------------------------
__device__ __forceinline__ uint32_t smem_to_u32(const void* p) {
    uint32_t a;
    asm("{ .reg .u64 t; cvta.to.shared.u64 t, %1; cvt.u32.u64 %0, t; }"
        : "=r"(a) : "l"(p));
    return a;
}
__device__ __forceinline__ void cp16(uint32_t dst, const void* src) {
    asm volatile("cp.async.cg.shared.global [%0], [%1], 16;" :: "r"(dst), "l"(src));
}
__device__ __forceinline__ void ldmatrix_x4(uint32_t* r, uint32_t addr) {
    asm volatile("ldmatrix.sync.aligned.m8n8.x4.shared.b16 {%0,%1,%2,%3}, [%4];"
                 : "=r"(r[0]), "=r"(r[1]), "=r"(r[2]), "=r"(r[3]) : "r"(addr));
}
__device__ __forceinline__ void mma_f16(float* c, const uint32_t* a, const uint32_t* b) {
    asm volatile(
        "mma.sync.aligned.m16n8k16.row.col.f32.f16.f16.f32 "
        "{%0,%1,%2,%3}, {%4,%5,%6,%7}, {%8,%9}, {%0,%1,%2,%3};"
        : "+f"(c[0]), "+f"(c[1]), "+f"(c[2]), "+f"(c[3])
        : "r"(a[0]), "r"(a[1]), "r"(a[2]), "r"(a[3]), "r"(b[0]), "r"(b[1]));
}

// ---------------- index width detection --------------------------------------
__global__ void detect_idx_kernel(const unsigned int* __restrict__ w) {
    int is64 = 1;
    for (int i = 1; i < 512; i += 2)
        if (w[i] != 0u) { is64 = 0; break; }
    g_idx_is64 = is64;
}

// ---------------- feat -> fp16 ------------------------------------------------
__global__ __launch_bounds__(256) void convert_A_kernel(const float* __restrict__ A) {
    const size_t i = (size_t)blockIdx.x * 256 + threadIdx.x;
    const float4 v = reinterpret_cast<const float4*>(A)[i];
    __half2 h0 = __floats2half2_rn(v.x, v.y);
    __half2 h1 = __floats2half2_rn(v.z, v.w);
    uint2 packed;
    packed.x = *reinterpret_cast<uint32_t*>(&h0);
    packed.y = *reinterpret_cast<uint32_t*>(&h1);
    reinterpret_cast<uint2*>(g_A16)[i] = packed;
}

// ---------------- W -> B^T fp16: rows [0,512)=Wt^T, [512,1024)=(Wp-Wt)^T ------
__global__ __launch_bounds__(256) void convert_W_kernel(const float* __restrict__ Wt,
                                                        const float* __restrict__ Wp) {
    const int idx = blockIdx.x * 256 + threadIdx.x;   // [0, 1024*512)
    const int n = idx >> 9;
    const int k = idx & 511;
    const int nc = n & 511;
    float w;
    if (n < 512) w = Wt[(size_t)k * 512 + nc];
    else         w = Wp[(size_t)k * 512 + nc] - Wt[(size_t)k * 512 + nc];
    g_BT16[(size_t)n * F + k] = __float2half_rn(w);
}

// ---------------- persistent HMMA dual GEMM -----------------------------------
// C[65536 x 1024] = A16 @ [Wt | Wp-Wt], fp16 in, fp32 acc.
// 296 CTAs, each walks ~14 output tiles; cp.async pipeline runs continuously
// across tile boundaries (step stream s: w = s/8, kt = s%8).

__device__ __forceinline__ void tile_coords(int bid, int w, int& m0, int& n0) {
    const int g     = bid + w * NCTA;
    const int group = g >> 8;               // 32 m-blocks x 8 n-blocks per group
    const int inner = g & 255;
    n0 = (inner >> 5) * BN;
    m0 = ((group << 5) | (inner & 31)) * BM;
}

__device__ __forceinline__ void load_step(uint32_t sm_base, int bid, int s, int tid) {
    const int w  = s >> 3;
    const int kt = s & 7;
    int m0, n0;
    tile_coords(bid, w, m0, n0);
    const int kc = kt * BK;
    const int stage = s % STAGES;
    const uint32_t smA = sm_base + stage * STAGE_BYTES;
    const uint32_t smB = smA + TILE_BYTES;
#pragma unroll
    for (int i = 0; i < 8; i++) {
        const int q = tid + i * GEMM_THREADS;   // 0..1023
        const int r = q >> 3;
        const int c = q & 7;
        cp16(smA + r * ROWB + c * 16,
             g_A16 + (size_t)(m0 + r) * F + kc + c * 8);
    }
#pragma unroll
    for (int i = 0; i < 8; i++) {
        const int q = tid + i * GEMM_THREADS;
        const int r = q >> 3;
        const int c = q & 7;
        cp16(smB + r * ROWB + c * 16,
             g_BT16 + (size_t)(n0 + r) * F + kc + c * 8);
    }
    asm volatile("cp.async.commit_group;" ::: "memory");
}

__global__ __launch_bounds__(GEMM_THREADS, 2) void gemm_kernel() {
    extern __shared__ __align__(128) char smem[];
    const uint32_t sm_base = smem_to_u32(smem);
    const int tid = threadIdx.x;
    const int wid = tid >> 5;
    const int lid = tid & 31;
    const int bid = blockIdx.x;

    const int W   = (NTILES - bid + NCTA - 1) / NCTA;   // 13 or 14
    const int TOT = W * KSTEPS;

    // warp layout: 2 (m) x 2 (n); warp tile 64m x 64n
    const int wm0 = (wid >> 1) * 64;
    const int wn0 = (wid & 1) * 64;

    float acc[4][8][4];
#pragma unroll
    for (int i = 0; i < 4; i++)
#pragma unroll
        for (int j = 0; j < 8; j++)
#pragma unroll
            for (int q = 0; q < 4; q++) acc[i][j][q] = 0.f;

    // prologue: 2 steps in flight
    load_step(sm_base, bid, 0, tid);
    load_step(sm_base, bid, 1, tid);

    const int a_row_off = wm0 + (lid & 15);
    const int a_col_off = (lid >> 4) * 8;
    const int b_row_off = wn0 + ((lid & 16) >> 1) + (lid & 7);
    const int b_col_off = ((lid & 8) ? 8 : 0);

    const int er = lid >> 2;
    const int ec = (lid & 3) * 2;

    for (int s = 0; s < TOT; s++) {
        if (s + 1 < TOT) asm volatile("cp.async.wait_group 1;" ::: "memory");
        else             asm volatile("cp.async.wait_group 0;" ::: "memory");
        // all warps done with step s-1 -> stage (s+2)%3 == (s-1)%3 is free
        __syncthreads();

        if (s + 2 < TOT)
            load_step(sm_base, bid, s + 2, tid);

        const int st = s % STAGES;
        const uint32_t smA = sm_base + st * STAGE_BYTES;
        const uint32_t smB = smA + TILE_BYTES;

        // fragment double buffer over 4 ks steps
        uint32_t a[2][4][4], b[2][8][2];
        {
#pragma unroll
            for (int i = 0; i < 4; i++)
                ldmatrix_x4(a[0][i], smA + (a_row_off + i * 16) * ROWB
                                         + a_col_off * 2);
#pragma unroll
            for (int j2 = 0; j2 < 4; j2++) {
                uint32_t r[4];
                ldmatrix_x4(r, smB + (b_row_off + j2 * 16) * ROWB
                                   + b_col_off * 2);
                b[0][j2 * 2 + 0][0] = r[0]; b[0][j2 * 2 + 0][1] = r[1];
                b[0][j2 * 2 + 1][0] = r[2]; b[0][j2 * 2 + 1][1] = r[3];
            }
        }
#pragma unroll
        for (int ks = 0; ks < 4; ks++) {
            const int cur = ks & 1;
            if (ks < 3) {
                const int nxt = cur ^ 1;
                const int col = (ks + 1) * 16;
#pragma unroll
                for (int i = 0; i < 4; i++)
                    ldmatrix_x4(a[nxt][i], smA + (a_row_off + i * 16) * ROWB
                                               + (col + a_col_off) * 2);
#pragma unroll
                for (int j2 = 0; j2 < 4; j2++) {
                    uint32_t r[4];
                    ldmatrix_x4(r, smB + (b_row_off + j2 * 16) * ROWB
                                       + (col + b_col_off) * 2);
                    b[nxt][j2 * 2 + 0][0] = r[0]; b[nxt][j2 * 2 + 0][1] = r[1];
                    b[nxt][j2 * 2 + 1][0] = r[2]; b[nxt][j2 * 2 + 1][1] = r[3];
                }
            }
#pragma unroll
            for (int i = 0; i < 4; i++)
#pragma unroll
                for (int j = 0; j < 8; j++)
                    mma_f16(acc[i][j], a[cur][i], b[cur][j]);
        }

        // end of an output tile: epilogue + reset accumulators
        if ((s & 7) == 7) {
            int m0, n0;
            tile_coords(bid, s >> 3, m0, n0);
            const bool is_theta = (n0 < 512);
            const int nc0 = n0 & 511;
#pragma unroll
            for (int i = 0; i < 4; i++) {
#pragma unroll
                for (int j = 0; j < 8; j++) {
                    const int m = m0 + wm0 + i * 16 + er;
                    const int n = nc0 + wn0 + j * 8 + ec;
                    float2 v0 = make_float2(acc[i][j][0], acc[i][j][1]);
                    float2 v1 = make_float2(acc[i][j][2], acc[i][j][3]);
                    if (is_theta) {
                        *reinterpret_cast<__half2*>(&g_theta16[(size_t)m * F + n]) =
                            __float22half2_rn(v0);
                        *reinterpret_cast<__half2*>(&g_theta16[(size_t)(m + 8) * F + n]) =
                            __float22half2_rn(v1);
                    } else {
                        *reinterpret_cast<float2*>(&g_hdst[(size_t)m * F + n])       = v0;
                        *reinterpret_cast<float2*>(&g_hdst[(size_t)(m + 8) * F + n]) = v1;
                    }
                    acc[i][j][0] = 0.f; acc[i][j][1] = 0.f;
                    acc[i][j][2] = 0.f; acc[i][j][3] = 0.f;
                }
            }
        }
    }
}

// ---------------- gather + max + add -------------------------------------------
// out[n][c] = max_j theta16[src[n][j]][c] + hdst[n][c]
__global__ __launch_bounds__(128) void gather_max_kernel(
    const void* __restrict__ src, float* __restrict__ out)
{
    const int n  = blockIdx.x;
    const int c4 = threadIdx.x;            // 0..127: 4 features each

    __shared__ unsigned int sidx[KNN];
    if (threadIdx.x < KNN) {
        if (g_idx_is64) {
            sidx[threadIdx.x] = (unsigned int)((const unsigned long long*)src)
                                    [(size_t)n * KNN + threadIdx.x] & 0xFFFFu;
        } else {
            sidx[threadIdx.x] = ((const unsigned int*)src)
                                    [(size_t)n * KNN + threadIdx.x] & 0xFFFFu;
        }
    }
    __syncthreads();

    const uint2* __restrict__ t16 = reinterpret_cast<const uint2*>(g_theta16);

    uint2 raw = t16[(size_t)sidx[0] * (F / 4) + c4];
    __half2 m0 = *reinterpret_cast<__half2*>(&raw.x);
    __half2 m1 = *reinterpret_cast<__half2*>(&raw.y);
#pragma unroll
    for (int j = 1; j < KNN; j++) {
        uint2 r = t16[(size_t)sidx[j] * (F / 4) + c4];
        m0 = __hmax2(m0, *reinterpret_cast<__half2*>(&r.x));
        m1 = __hmax2(m1, *reinterpret_cast<__half2*>(&r.y));
    }

    const float4 hd = reinterpret_cast<const float4*>(g_hdst)[(size_t)n * (F / 4) + c4];

    const float2 f0 = __half22float2(m0);
    const float2 f1 = __half22float2(m1);
    float4 r;
    r.x = f0.x + hd.x; r.y = f0.y + hd.y;
    r.z = f1.x + hd.z; r.w = f1.y + hd.w;
    reinterpret_cast<float4*>(out)[(size_t)n * (F / 4) + c4] = r;
}

// ---------------------------------------------------------------------------------
extern "C" void kernel_launch(void* const* d_in, const int* in_sizes, int n_in,
                              void* d_out, int out_size)
{
    const void*  src  = nullptr;
    const float* feat = nullptr;
    const float* Wt   = nullptr;
    const float* Wp   = nullptr;

    for (int i = 0; i < n_in; i++) {
        const int s = in_sizes[i];
        if (s == NN * KNN)      src  = d_in[i];
        else if (s == NN * F)   feat = (const float*)d_in[i];
        else if (s == F * F) {
            if (!Wt) Wt = (const float*)d_in[i];
            else     Wp = (const float*)d_in[i];
        }
    }

    cudaFuncSetAttribute(gemm_kernel,
                         cudaFuncAttributeMaxDynamicSharedMemorySize, SM_TOTAL);

    detect_idx_kernel<<<1, 1>>>((const unsigned int*)src);
    convert_A_kernel<<<(NN * (F / 4)) / 256, 256>>>(feat);
    convert_W_kernel<<<(NOUT * F) / 256, 256>>>(Wt, Wp);
    gemm_kernel<<<NCTA, GEMM_THREADS, SM_TOTAL>>>();
    gather_max_kernel<<<NN, 128>>>(src, (float*)d_out);
}

// round 11
// speedup vs baseline: 1.0628x; 1.0059x over previous
#include <cuda_runtime.h>
#include <cuda_fp16.h>
#include <cstdint>
#include <cstddef>

#define NN   65536
#define F    512
#define KNN  16
#define NOUT 1024

#define BM 128
#define BN 64
#define BK 64
#define STAGES 2
#define GEMM_THREADS 128           // 4 warps: 2 (m) x 2 (n), warp tile 64x32
#define NKTILES (F / BK)           // 8

// smem row: 64 fp16 data + 8 pad = 72 elems = 144B
#define ROWB 144
#define A_TILE_BYTES (BM * ROWB)                    // 18432
#define B_TILE_BYTES (BN * ROWB)                    // 9216
#define STAGE_BYTES  (A_TILE_BYTES + B_TILE_BYTES)  // 27648
#define SM_TOTAL (STAGES * STAGE_BYTES)             // 55296 (x4 CTAs = 221KB/SM)

// ---------------- scratch (__device__ globals) ------------------------------
__device__ __align__(1024) float   g_hdst[(size_t)NN * F];     // 128MB (phi-theta)
__device__ __align__(1024) __half  g_theta16[(size_t)NN * F];  // 64MB
__device__ __align__(1024) __half  g_A16[(size_t)NN * F];      // 64MB
__device__ __align__(1024) __half  g_BT16[(size_t)NOUT * F];   // 1MB
__device__ int g_idx_is64;

// ---------------- helpers ----------------------------------------------------
__device__ __forceinline__ uint32_t smem_to_u32(const void* p) {
    uint32_t a;
    asm("{ .reg .u64 t; cvta.to.shared.u64 t, %1; cvt.u32.u64 %0, t; }"
        : "=r"(a) : "l"(p));
    return a;
}
__device__ __forceinline__ void cp16(uint32_t dst, const void* src) {
    asm volatile("cp.async.cg.shared.global [%0], [%1], 16;" :: "r"(dst), "l"(src));
}
__device__ __forceinline__ void ldmatrix_x4(uint32_t* r, uint32_t addr) {
    asm volatile("ldmatrix.sync.aligned.m8n8.x4.shared.b16 {%0,%1,%2,%3}, [%4];"
                 : "=r"(r[0]), "=r"(r[1]), "=r"(r[2]), "=r"(r[3]) : "r"(addr));
}
__device__ __forceinline__ void mma_f16(float* c, const uint32_t* a, const uint32_t* b) {
    asm volatile(
        "mma.sync.aligned.m16n8k16.row.col.f32.f16.f16.f32 "
        "{%0,%1,%2,%3}, {%4,%5,%6,%7}, {%8,%9}, {%0,%1,%2,%3};"
        : "+f"(c[0]), "+f"(c[1]), "+f"(c[2]), "+f"(c[3])
        : "r"(a[0]), "r"(a[1]), "r"(a[2]), "r"(a[3]), "r"(b[0]), "r"(b[1]));
}

// ---------------- index width detection (1 warp) ------------------------------
__global__ void detect_idx_kernel(const unsigned int* __restrict__ w) {
    const int lane = threadIdx.x;
    int bad = 0;
    for (int i = 1 + 2 * lane; i < 512; i += 64)
        if (w[i] != 0u) bad = 1;
    const int any_bad = __any_sync(0xFFFFFFFFu, bad);
    if (lane == 0) g_idx_is64 = any_bad ? 0 : 1;
}

// ---------------- feat -> fp16 ------------------------------------------------
__global__ __launch_bounds__(256) void convert_A_kernel(const float* __restrict__ A) {
    const size_t i = (size_t)blockIdx.x * 256 + threadIdx.x;
    const float4 v = reinterpret_cast<const float4*>(A)[i];
    __half2 h0 = __floats2half2_rn(v.x, v.y);
    __half2 h1 = __floats2half2_rn(v.z, v.w);
    uint2 packed;
    packed.x = *reinterpret_cast<uint32_t*>(&h0);
    packed.y = *reinterpret_cast<uint32_t*>(&h1);
    reinterpret_cast<uint2*>(g_A16)[i] = packed;
}

// ---------------- W -> B^T fp16: rows [0,512)=Wt^T, [512,1024)=(Wp-Wt)^T ------
__global__ __launch_bounds__(256) void convert_W_kernel(const float* __restrict__ Wt,
                                                        const float* __restrict__ Wp) {
    const int idx = blockIdx.x * 256 + threadIdx.x;   // [0, 1024*512)
    const int n = idx >> 9;
    const int k = idx & 511;
    const int nc = n & 511;
    float w;
    if (n < 512) w = Wt[(size_t)k * 512 + nc];
    else         w = Wp[(size_t)k * 512 + nc] - Wt[(size_t)k * 512 + nc];
    g_BT16[(size_t)n * F + k] = __float2half_rn(w);
}

// ---------------- HMMA dual GEMM ----------------------------------------------
// C[65536 x 1024] = A16 @ [Wt | Wp-Wt], fp16 in, fp32 acc.
// CTA tile 128x64, 4 warps (2m x 2n), warp tile 64x32, 2 stages, 4 CTAs/SM.
__device__ __forceinline__ void load_tile(uint32_t sm_base, int stage, int t,
                                          int m0, int n0, int tid) {
    const int kc = t * BK;
    const uint32_t smA = sm_base + stage * STAGE_BYTES;
    const uint32_t smB = smA + A_TILE_BYTES;
#pragma unroll
    for (int i = 0; i < 8; i++) {               // A: 128 rows x 8 chunks = 1024
        const int q = tid + i * GEMM_THREADS;
        const int r = q >> 3;
        const int c = q & 7;
        cp16(smA + r * ROWB + c * 16,
             g_A16 + (size_t)(m0 + r) * F + kc + c * 8);
    }
#pragma unroll
    for (int i = 0; i < 4; i++) {               // B: 64 rows x 8 chunks = 512
        const int q = tid + i * GEMM_THREADS;
        const int r = q >> 3;
        const int c = q & 7;
        cp16(smB + r * ROWB + c * 16,
             g_BT16 + (size_t)(n0 + r) * F + kc + c * 8);
    }
    asm volatile("cp.async.commit_group;" ::: "memory");
}

__global__ __launch_bounds__(GEMM_THREADS, 4) void gemm_kernel() {
    extern __shared__ __align__(128) char smem[];
    const uint32_t sm_base = smem_to_u32(smem);
    const int tid = threadIdx.x;
    const int wid = tid >> 5;
    const int lid = tid & 31;

    // block swizzle: groups of 32 m-blocks sweep all 16 n-blocks (A stays in L2)
    const int bid   = blockIdx.x;
    const int group = bid >> 9;            // / (32*16)
    const int inner = bid & 511;
    const int n_blk = inner >> 5;
    const int m_blk = (group << 5) | (inner & 31);
    const int m0 = m_blk * BM;
    const int n0 = n_blk * BN;

    // warp layout: 2 (m) x 2 (n); warp tile 64m x 32n
    const int wm0 = (wid >> 1) * 64;
    const int wn0 = (wid & 1) * 32;

    float acc[4][4][4];
#pragma unroll
    for (int i = 0; i < 4; i++)
#pragma unroll
        for (int j = 0; j < 4; j++)
#pragma unroll
            for (int q = 0; q < 4; q++) acc[i][j][q] = 0.f;

    load_tile(sm_base, 0, 0, m0, n0, tid);
    load_tile(sm_base, 1, 1, m0, n0, tid);

    const int a_row_off = wm0 + (lid & 15);
    const int a_col_off = (lid >> 4) * 8;
    const int b_row_off = wn0 + ((lid & 16) >> 1) + (lid & 7);
    const int b_col_off = ((lid & 8) ? 8 : 0);

    for (int t = 0; t < NKTILES; t++) {
        const int st = t & 1;
        if (t + 1 < NKTILES) asm volatile("cp.async.wait_group 1;" ::: "memory");
        else                 asm volatile("cp.async.wait_group 0;" ::: "memory");
        __syncthreads();

        const uint32_t smA = sm_base + st * STAGE_BYTES;
        const uint32_t smB = smA + A_TILE_BYTES;

        // single-buffered fragments; 4 warps/SMSP hide LDSM latency
#pragma unroll
        for (int ks = 0; ks < 4; ks++) {
            const int col = ks * 16;
            uint32_t a[4][4], b[4][2];
#pragma unroll
            for (int i = 0; i < 4; i++)
                ldmatrix_x4(a[i], smA + (a_row_off + i * 16) * ROWB
                                      + (col + a_col_off) * 2);
#pragma unroll
            for (int j2 = 0; j2 < 2; j2++) {
                uint32_t r[4];
                ldmatrix_x4(r, smB + (b_row_off + j2 * 16) * ROWB
                                   + (col + b_col_off) * 2);
                b[j2 * 2 + 0][0] = r[0]; b[j2 * 2 + 0][1] = r[1];
                b[j2 * 2 + 1][0] = r[2]; b[j2 * 2 + 1][1] = r[3];
            }
#pragma unroll
            for (int i = 0; i < 4; i++)
#pragma unroll
                for (int j = 0; j < 4; j++)
                    mma_f16(acc[i][j], a[i], b[j]);
        }

        // all warps done reading stage st before overwriting it
        __syncthreads();
        if (t + 2 < NKTILES)
            load_tile(sm_base, st, t + 2, m0, n0, tid);
    }

    // epilogue: theta blocks -> fp16 mirror; hdst blocks -> fp32
    const bool is_theta = (n0 < 512);
    const int nc0 = n0 & 511;
    const int er = lid >> 2;
    const int ec = (lid & 3) * 2;
#pragma unroll
    for (int i = 0; i < 4; i++) {
#pragma unroll
        for (int j = 0; j < 4; j++) {
            const int m = m0 + wm0 + i * 16 + er;
            const int n = nc0 + wn0 + j * 8 + ec;
            float2 v0 = make_float2(acc[i][j][0], acc[i][j][1]);
            float2 v1 = make_float2(acc[i][j][2], acc[i][j][3]);
            if (is_theta) {
                *reinterpret_cast<__half2*>(&g_theta16[(size_t)m * F + n]) =
                    __float22half2_rn(v0);
                *reinterpret_cast<__half2*>(&g_theta16[(size_t)(m + 8) * F + n]) =
                    __float22half2_rn(v1);
            } else {
                *reinterpret_cast<float2*>(&g_hdst[(size_t)m * F + n])       = v0;
                *reinterpret_cast<float2*>(&g_hdst[(size_t)(m + 8) * F + n]) = v1;
            }
        }
    }
}

// ---------------- gather + max + add -------------------------------------------
// out[n][c] = max_j theta16[src[n][j]][c] + hdst[n][c]
__global__ __launch_bounds__(128) void gather_max_kernel(
    const void* __restrict__ src, float* __restrict__ out)
{
    const int n  = blockIdx.x;
    const int c4 = threadIdx.x;            // 0..127: 4 features each

    __shared__ unsigned int sidx[KNN];
    if (threadIdx.x < KNN) {
        if (g_idx_is64) {
            sidx[threadIdx.x] = (unsigned int)((const unsigned long long*)src)
                                    [(size_t)n * KNN + threadIdx.x] & 0xFFFFu;
        } else {
            sidx[threadIdx.x] = ((const unsigned int*)src)
                                    [(size_t)n * KNN + threadIdx.x] & 0xFFFFu;
        }
    }
    __syncthreads();

    const uint2* __restrict__ t16 = reinterpret_cast<const uint2*>(g_theta16);

    uint2 raw = t16[(size_t)sidx[0] * (F / 4) + c4];
    __half2 m0 = *reinterpret_cast<__half2*>(&raw.x);
    __half2 m1 = *reinterpret_cast<__half2*>(&raw.y);
#pragma unroll
    for (int j = 1; j < KNN; j++) {
        uint2 r = t16[(size_t)sidx[j] * (F / 4) + c4];
        m0 = __hmax2(m0, *reinterpret_cast<__half2*>(&r.x));
        m1 = __hmax2(m1, *reinterpret_cast<__half2*>(&r.y));
    }

    const float4 hd = reinterpret_cast<const float4*>(g_hdst)[(size_t)n * (F / 4) + c4];

    const float2 f0 = __half22float2(m0);
    const float2 f1 = __half22float2(m1);
    float4 r;
    r.x = f0.x + hd.x; r.y = f0.y + hd.y;
    r.z = f1.x + hd.z; r.w = f1.y + hd.w;
    reinterpret_cast<float4*>(out)[(size_t)n * (F / 4) + c4] = r;
}

// ---------------------------------------------------------------------------------
extern "C" void kernel_launch(void* const* d_in, const int* in_sizes, int n_in,
                              void* d_out, int out_size)
{
    const void*  src  = nullptr;
    const float* feat = nullptr;
    const float* Wt   = nullptr;
    const float* Wp   = nullptr;

    for (int i = 0; i < n_in; i++) {
        const int s = in_sizes[i];
        if (s == NN * KNN)      src  = d_in[i];
        else if (s == NN * F)   feat = (const float*)d_in[i];
        else if (s == F * F) {
            if (!Wt) Wt = (const float*)d_in[i];
            else     Wp = (const float*)d_in[i];
        }
    }

    cudaFuncSetAttribute(gemm_kernel,
                         cudaFuncAttributeMaxDynamicSharedMemorySize, SM_TOTAL);

    detect_idx_kernel<<<1, 32>>>((const unsigned int*)src);
    convert_A_kernel<<<(NN * (F / 4)) / 256, 256>>>(feat);
    convert_W_kernel<<<(NOUT * F) / 256, 256>>>(Wt, Wp);
    gemm_kernel<<<(NN / BM) * (NOUT / BN), GEMM_THREADS, SM_TOTAL>>>();
    gather_max_kernel<<<NN, 128>>>(src, (float*)d_out);
}

// round 12
// speedup vs baseline: 1.1231x; 1.0567x over previous
#include <cuda_runtime.h>
#include <cuda_fp16.h>
#include <cstdint>
#include <cstddef>

#define NN   65536
#define F    512
#define KNN  16
#define NOUT 1024

#define BM 128
#define BN 64
#define BK 64
#define STAGES 2
#define GEMM_THREADS 128           // 4 warps: 2 (m) x 2 (n), warp tile 64x32
#define NKTILES (F / BK)           // 8

// smem row: 64 fp16 data + 8 pad = 72 elems = 144B
#define ROWB 144
#define A_TILE_BYTES (BM * ROWB)                    // 18432
#define B_TILE_BYTES (BN * ROWB)                    // 9216
#define STAGE_BYTES  (A_TILE_BYTES + B_TILE_BYTES)  // 27648
#define SM_TOTAL (STAGES * STAGE_BYTES)             // 55296 (x4 CTAs = 221KB/SM)

// ---------------- scratch (__device__ globals) ------------------------------
__device__ __align__(1024) __half  g_hdst16[(size_t)NN * F];   // 64MB (phi-theta)
__device__ __align__(1024) __half  g_theta16[(size_t)NN * F];  // 64MB
__device__ __align__(1024) __half  g_A16[(size_t)NN * F];      // 64MB
__device__ __align__(1024) __half  g_BT16[(size_t)NOUT * F];   // 1MB
__device__ int g_idx_is64;

// ---------------- helpers ----------------------------------------------------
__device__ __forceinline__ uint32_t smem_to_u32(const void* p) {
    uint32_t a;
    asm("{ .reg .u64 t; cvta.to.shared.u64 t, %1; cvt.u32.u64 %0, t; }"
        : "=r"(a) : "l"(p));
    return a;
}
__device__ __forceinline__ void cp16(uint32_t dst, const void* src) {
    asm volatile("cp.async.cg.shared.global [%0], [%1], 16;" :: "r"(dst), "l"(src));
}
__device__ __forceinline__ void ldmatrix_x4(uint32_t* r, uint32_t addr) {
    asm volatile("ldmatrix.sync.aligned.m8n8.x4.shared.b16 {%0,%1,%2,%3}, [%4];"
                 : "=r"(r[0]), "=r"(r[1]), "=r"(r[2]), "=r"(r[3]) : "r"(addr));
}
__device__ __forceinline__ void mma_f16(float* c, const uint32_t* a, const uint32_t* b) {
    asm volatile(
        "mma.sync.aligned.m16n8k16.row.col.f32.f16.f16.f32 "
        "{%0,%1,%2,%3}, {%4,%5,%6,%7}, {%8,%9}, {%0,%1,%2,%3};"
        : "+f"(c[0]), "+f"(c[1]), "+f"(c[2]), "+f"(c[3])
        : "r"(a[0]), "r"(a[1]), "r"(a[2]), "r"(a[3]), "r"(b[0]), "r"(b[1]));
}

// ---------------- index width detection (1 warp) ------------------------------
__global__ void detect_idx_kernel(const unsigned int* __restrict__ w) {
    const int lane = threadIdx.x;
    int bad = 0;
    for (int i = 1 + 2 * lane; i < 512; i += 64)
        if (w[i] != 0u) bad = 1;
    const int any_bad = __any_sync(0xFFFFFFFFu, bad);
    if (lane == 0) g_idx_is64 = any_bad ? 0 : 1;
}

// ---------------- feat -> fp16 ------------------------------------------------
__global__ __launch_bounds__(256) void convert_A_kernel(const float* __restrict__ A) {
    const size_t i = (size_t)blockIdx.x * 256 + threadIdx.x;
    const float4 v = reinterpret_cast<const float4*>(A)[i];
    __half2 h0 = __floats2half2_rn(v.x, v.y);
    __half2 h1 = __floats2half2_rn(v.z, v.w);
    uint2 packed;
    packed.x = *reinterpret_cast<uint32_t*>(&h0);
    packed.y = *reinterpret_cast<uint32_t*>(&h1);
    reinterpret_cast<uint2*>(g_A16)[i] = packed;
}

// ---------------- W -> B^T fp16: rows [0,512)=Wt^T, [512,1024)=(Wp-Wt)^T ------
__global__ __launch_bounds__(256) void convert_W_kernel(const float* __restrict__ Wt,
                                                        const float* __restrict__ Wp) {
    const int idx = blockIdx.x * 256 + threadIdx.x;   // [0, 1024*512)
    const int n = idx >> 9;
    const int k = idx & 511;
    const int nc = n & 511;
    float w;
    if (n < 512) w = Wt[(size_t)k * 512 + nc];
    else         w = Wp[(size_t)k * 512 + nc] - Wt[(size_t)k * 512 + nc];
    g_BT16[(size_t)n * F + k] = __float2half_rn(w);
}

// ---------------- HMMA dual GEMM ----------------------------------------------
// C[65536 x 1024] = A16 @ [Wt | Wp-Wt], fp16 in, fp32 acc.
// CTA tile 128x64, 4 warps (2m x 2n), warp tile 64x32, 2 stages, 4 CTAs/SM.
__device__ __forceinline__ void load_tile(uint32_t sm_base, int stage, int t,
                                          int m0, int n0, int tid) {
    const int kc = t * BK;
    const uint32_t smA = sm_base + stage * STAGE_BYTES;
    const uint32_t smB = smA + A_TILE_BYTES;
#pragma unroll
    for (int i = 0; i < 8; i++) {               // A: 128 rows x 8 chunks = 1024
        const int q = tid + i * GEMM_THREADS;
        const int r = q >> 3;
        const int c = q & 7;
        cp16(smA + r * ROWB + c * 16,
             g_A16 + (size_t)(m0 + r) * F + kc + c * 8);
    }
#pragma unroll
    for (int i = 0; i < 4; i++) {               // B: 64 rows x 8 chunks = 512
        const int q = tid + i * GEMM_THREADS;
        const int r = q >> 3;
        const int c = q & 7;
        cp16(smB + r * ROWB + c * 16,
             g_BT16 + (size_t)(n0 + r) * F + kc + c * 8);
    }
    asm volatile("cp.async.commit_group;" ::: "memory");
}

__global__ __launch_bounds__(GEMM_THREADS, 4) void gemm_kernel() {
    extern __shared__ __align__(128) char smem[];
    const uint32_t sm_base = smem_to_u32(smem);
    const int tid = threadIdx.x;
    const int wid = tid >> 5;
    const int lid = tid & 31;

    // block swizzle: groups of 32 m-blocks sweep all 16 n-blocks (A stays in L2)
    const int bid   = blockIdx.x;
    const int group = bid >> 9;            // / (32*16)
    const int inner = bid & 511;
    const int n_blk = inner >> 5;
    const int m_blk = (group << 5) | (inner & 31);
    const int m0 = m_blk * BM;
    const int n0 = n_blk * BN;

    // warp layout: 2 (m) x 2 (n); warp tile 64m x 32n
    const int wm0 = (wid >> 1) * 64;
    const int wn0 = (wid & 1) * 32;

    float acc[4][4][4];
#pragma unroll
    for (int i = 0; i < 4; i++)
#pragma unroll
        for (int j = 0; j < 4; j++)
#pragma unroll
            for (int q = 0; q < 4; q++) acc[i][j][q] = 0.f;

    load_tile(sm_base, 0, 0, m0, n0, tid);
    load_tile(sm_base, 1, 1, m0, n0, tid);

    const int a_row_off = wm0 + (lid & 15);
    const int a_col_off = (lid >> 4) * 8;
    const int b_row_off = wn0 + ((lid & 16) >> 1) + (lid & 7);
    const int b_col_off = ((lid & 8) ? 8 : 0);

    for (int t = 0; t < NKTILES; t++) {
        const int st = t & 1;
        if (t + 1 < NKTILES) asm volatile("cp.async.wait_group 1;" ::: "memory");
        else                 asm volatile("cp.async.wait_group 0;" ::: "memory");
        __syncthreads();

        const uint32_t smA = sm_base + st * STAGE_BYTES;
        const uint32_t smB = smA + A_TILE_BYTES;

        // single-buffered fragments; 4 warps/SMSP hide LDSM latency
#pragma unroll
        for (int ks = 0; ks < 4; ks++) {
            const int col = ks * 16;
            uint32_t a[4][4], b[4][2];
#pragma unroll
            for (int i = 0; i < 4; i++)
                ldmatrix_x4(a[i], smA + (a_row_off + i * 16) * ROWB
                                      + (col + a_col_off) * 2);
#pragma unroll
            for (int j2 = 0; j2 < 2; j2++) {
                uint32_t r[4];
                ldmatrix_x4(r, smB + (b_row_off + j2 * 16) * ROWB
                                   + (col + b_col_off) * 2);
                b[j2 * 2 + 0][0] = r[0]; b[j2 * 2 + 0][1] = r[1];
                b[j2 * 2 + 1][0] = r[2]; b[j2 * 2 + 1][1] = r[3];
            }
#pragma unroll
            for (int i = 0; i < 4; i++)
#pragma unroll
                for (int j = 0; j < 4; j++)
                    mma_f16(acc[i][j], a[i], b[j]);
        }

        // all warps done reading stage st before overwriting it
        __syncthreads();
        if (t + 2 < NKTILES)
            load_tile(sm_base, st, t + 2, m0, n0, tid);
    }

    // epilogue: both halves -> fp16 (theta mirror / hdst)
    __half* outbase = (n0 < 512) ? g_theta16 : g_hdst16;
    const int nc0 = n0 & 511;
    const int er = lid >> 2;
    const int ec = (lid & 3) * 2;
#pragma unroll
    for (int i = 0; i < 4; i++) {
#pragma unroll
        for (int j = 0; j < 4; j++) {
            const int m = m0 + wm0 + i * 16 + er;
            const int n = nc0 + wn0 + j * 8 + ec;
            float2 v0 = make_float2(acc[i][j][0], acc[i][j][1]);
            float2 v1 = make_float2(acc[i][j][2], acc[i][j][3]);
            *reinterpret_cast<__half2*>(&outbase[(size_t)m * F + n]) =
                __float22half2_rn(v0);
            *reinterpret_cast<__half2*>(&outbase[(size_t)(m + 8) * F + n]) =
                __float22half2_rn(v1);
        }
    }
}

// ---------------- gather + max + add -------------------------------------------
// out[n][c] = max_j theta16[src[n][j]][c] + hdst16[n][c]
__global__ __launch_bounds__(128) void gather_max_kernel(
    const void* __restrict__ src, float* __restrict__ out)
{
    const int n  = blockIdx.x;
    const int c4 = threadIdx.x;            // 0..127: 4 features each

    __shared__ unsigned int sidx[KNN];
    if (threadIdx.x < KNN) {
        if (g_idx_is64) {
            sidx[threadIdx.x] = (unsigned int)((const unsigned long long*)src)
                                    [(size_t)n * KNN + threadIdx.x] & 0xFFFFu;
        } else {
            sidx[threadIdx.x] = ((const unsigned int*)src)
                                    [(size_t)n * KNN + threadIdx.x] & 0xFFFFu;
        }
    }
    __syncthreads();

    const uint2* __restrict__ t16 = reinterpret_cast<const uint2*>(g_theta16);

    uint2 raw = t16[(size_t)sidx[0] * (F / 4) + c4];
    __half2 m0 = *reinterpret_cast<__half2*>(&raw.x);
    __half2 m1 = *reinterpret_cast<__half2*>(&raw.y);
#pragma unroll
    for (int j = 1; j < KNN; j++) {
        uint2 r = t16[(size_t)sidx[j] * (F / 4) + c4];
        m0 = __hmax2(m0, *reinterpret_cast<__half2*>(&r.x));
        m1 = __hmax2(m1, *reinterpret_cast<__half2*>(&r.y));
    }

    const uint2 hdraw =
        reinterpret_cast<const uint2*>(g_hdst16)[(size_t)n * (F / 4) + c4];
    const float2 hd0 = __half22float2(*reinterpret_cast<const __half2*>(&hdraw.x));
    const float2 hd1 = __half22float2(*reinterpret_cast<const __half2*>(&hdraw.y));

    const float2 f0 = __half22float2(m0);
    const float2 f1 = __half22float2(m1);
    float4 r;
    r.x = f0.x + hd0.x; r.y = f0.y + hd0.y;
    r.z = f1.x + hd1.x; r.w = f1.y + hd1.y;
    reinterpret_cast<float4*>(out)[(size_t)n * (F / 4) + c4] = r;
}

// ---------------------------------------------------------------------------------
extern "C" void kernel_launch(void* const* d_in, const int* in_sizes, int n_in,
                              void* d_out, int out_size)
{
    const void*  src  = nullptr;
    const float* feat = nullptr;
    const float* Wt   = nullptr;
    const float* Wp   = nullptr;

    for (int i = 0; i < n_in; i++) {
        const int s = in_sizes[i];
        if (s == NN * KNN)      src  = d_in[i];
        else if (s == NN * F)   feat = (const float*)d_in[i];
        else if (s == F * F) {
            if (!Wt) Wt = (const float*)d_in[i];
            else     Wp = (const float*)d_in[i];
        }
    }

    cudaFuncSetAttribute(gemm_kernel,
                         cudaFuncAttributeMaxDynamicSharedMemorySize, SM_TOTAL);

    detect_idx_kernel<<<1, 32>>>((const unsigned int*)src);
    convert_A_kernel<<<(NN * (F / 4)) / 256, 256>>>(feat);
    convert_W_kernel<<<(NOUT * F) / 256, 256>>>(Wt, Wp);
    gemm_kernel<<<(NN / BM) * (NOUT / BN), GEMM_THREADS, SM_TOTAL>>>();
    gather_max_kernel<<<NN, 128>>>(src, (float*)d_out);
}